// round 16
// baseline (speedup 1.0000x reference)
#include <cuda_runtime.h>
#include <cuda_fp16.h>

#define S_TOT 2048
#define B_DIM 64
#define N_DIM 256
#define EPSV 0.01f
#define INV_EPS 100.0f
#define THRESH 0.1f
#define MAX_ITER 100
#define LOG_EPS 1e-8f
#define THREADS 512

// E0_ij = exp((Cmin - C_ij)/eps) in fp16; row sums (of fp16 values) in fp32.
__device__ __align__(16) __half g_E0h[B_DIM * N_DIM];
__device__ float g_logS[B_DIM];
__device__ float g_invS[B_DIM];
__device__ float g_Cmin;

// ---------------------------------------------------------------------------
// Init: 16 blocks x 256 threads, PDL trigger at entry.
// ---------------------------------------------------------------------------
__global__ void __launch_bounds__(256) ot_init_kernel(const float* __restrict__ C) {
    cudaTriggerProgrammaticLaunchCompletion();

    __shared__ float sred[9];
    const int tid = threadIdx.x, l = tid & 31, w = tid >> 5;

    float mn = 3.402823466e38f;
    const float4* C4 = reinterpret_cast<const float4*>(C);
    #pragma unroll
    for (int k = 0; k < 16; k++) {
        const float4 c = C4[tid + 256 * k];
        mn = fminf(mn, fminf(fminf(c.x, c.y), fminf(c.z, c.w)));
    }
    #pragma unroll
    for (int o = 16; o; o >>= 1)
        mn = fminf(mn, __shfl_xor_sync(0xFFFFFFFFu, mn, o));
    if (l == 0) sred[w] = mn;
    __syncthreads();
    if (tid == 0) {
        float t = sred[0];
        #pragma unroll
        for (int k = 1; k < 8; k++) t = fminf(t, sred[k]);
        sred[8] = t;
        if (blockIdx.x == 0) g_Cmin = t;
    }
    __syncthreads();
    const float cmin = sred[8];

    #pragma unroll
    for (int rr = 0; rr < 4; rr++) {
        const int row = blockIdx.x * 4 + rr;
        const float val = __expf((cmin - C[(row << 8) + tid]) * INV_EPS);
        const __half hv = __float2half_rn(val);
        g_E0h[(row << 8) + tid] = hv;
        float f = __half2float(hv);
        #pragma unroll
        for (int o = 16; o; o >>= 1)
            f += __shfl_xor_sync(0xFFFFFFFFu, f, o);
        __syncthreads();
        if (l == 0) sred[w] = f;
        __syncthreads();
        if (tid == 0) {
            float s = 0.0f;
            #pragma unroll
            for (int k = 0; k < 8; k++) s += sred[k];
            g_logS[row] = __logf(s);
            g_invS[row] = 1.0f / s;
        }
    }
}

// smem layout (float offsets); E0h occupies floats [0,8192) as half[16384].
#define O_EUWT  8192    // float4[64]: (eu0, wt0, eu1, wt1)
#define O_SPART 8448    // spartA float4[384] @8448, spartB float4[384] @9984
#define O_SNU   11520   // Knu0 [256], Knu1 [256]
#define O_SEV   12032   // sev0 [256], sev1 [256]
#define O_SU    12544   // 2 x 64  (log-domain u, for du/err only)
#define O_SLM   12672   // 2 x 64  log(mu+1e-8)
#define O_SMU   12800   // 2 x 64  mu
#define O_SKMU  12928   // 2 x 64  (mu+1e-8)*e^(-cmin/eps)
#define O_SRED  13056   // 2 x 16: [8..15] du partials (16B aligned)
#define SMEM_FLOATS 13088

// err = same summation order: (((d0+d1)+(d2+d3))+((d4+d5)+(d6+d7)))
__device__ __forceinline__ float err_sum(const float* p) {
    const float4 a = *reinterpret_cast<const float4*>(p);
    const float4 b = *reinterpret_cast<const float4*>(p + 4);
    return ((a.x + a.y) + (a.z + a.w)) + ((b.x + b.y) + (b.z + b.w));
}

#define FFMA2(acc, a, b) \
    asm("fma.rn.f32x2 %0, %1, %2, %0;" : "+l"(acc) : "l"(a), "l"(b))
#define FADD2(acc, a) \
    asm("add.rn.f32x2 %0, %0, %1;" : "+l"(acc) : "l"(a))
#define BCAST2(dst, s) \
    asm("mov.b64 %0, {%1, %1};" : "=l"(dst) : "f"(s))
#define UNPACK2(lo, hi, p) \
    asm("mov.b64 {%0, %1}, %2;" : "=f"(lo), "=f"(hi) : "l"(p))

// ---------------------------------------------------------------------------
// Main: multiplicative Sinkhorn, fixed shift = cmin. 2 samples/block, 512 thr,
// fp16 E0 in shared. __launch_bounds__(512,4): 32-reg cap -> 4 blocks/SM
// (smem 51.1KB <= 57KB). Lean multiplicative body should fit without spills.
// ---------------------------------------------------------------------------
extern "C" __global__ void __launch_bounds__(THREADS, 4)
ot_main_kernel(const float* __restrict__ mu,
               const float* __restrict__ nu,
               float* __restrict__ out) {
    extern __shared__ float sm[];
    __half* sE0h = reinterpret_cast<__half*>(sm);

    const int tid = threadIdx.x;
    const int h   = tid >> 8;          // sample slot
    const int col = tid & 255;
    const int l   = tid & 31;
    const int ws  = (tid >> 5) & 7;
    const int qr  = tid >> 7;          // row-quarter (v mapping)
    const int cp  = tid & 127;         // col-pair

    float* sev_h  = sm + O_SEV + (h << 8);
    float* su_h   = sm + O_SU  + (h << 6);
    float* slm_h  = sm + O_SLM + (h << 6);
    float* smu_h  = sm + O_SMU + (h << 6);
    float* skmu_h = sm + O_SKMU + (h << 6);
    float* sred0  = sm + O_SRED;
    float* sred1  = sm + O_SRED + 16;
    float* sred_h = sm + O_SRED + (h << 4);
    float4* spartA = reinterpret_cast<float4*>(sm + O_SPART);
    float4* spartB = spartA + 384;

    const int s0 = blockIdx.x * 2, s1 = s0 + 1, s_h = s0 + h;

    // ---- independent prologue loads (overlap init via PDL) ----
    const float nuv = nu[s_h * N_DIM + col];
    float muv = 0.0f;
    if (col < B_DIM) muv = mu[s_h * B_DIM + col];

    cudaGridDependencySynchronize();

    const float cmin  = g_Cmin;
    const float en50  = __expf(-cmin * INV_EPS);   // e^(-cmin/eps)
    const float scale = __expf( cmin * INV_EPS);   // e^(+cmin/eps)

    // ================= PROLOGUE (one barrier) =================
    {
        const uint4* g4 = reinterpret_cast<const uint4*>(g_E0h);
        uint4* s4 = reinterpret_cast<uint4*>(sE0h);
        #pragma unroll
        for (int k = 0; k < 4; k++)
            s4[tid + THREADS * k] = g4[tid + THREADS * k];
    }
    sm[O_SNU + (h << 8) + col] = (nuv + LOG_EPS) * en50;   // Knu
    if (col < B_DIM) {
        const float mt = muv + LOG_EPS;
        const float lm = __logf(mt);
        smu_h[col]  = muv;
        slm_h[col]  = lm;
        skmu_h[col] = mt * en50;
        const float u1 = EPSV * (lm - g_logS[col]) + cmin;
        su_h[col] = u1;
        float d = fabsf(u1);
        #pragma unroll
        for (int o = 16; o; o >>= 1)
            d += __shfl_xor_sync(0xFFFFFFFFu, d, o);
        if (l == 0) sred_h[8 + ws] = d;
        const float eu = mt * g_invS[col];
        float* qp = sm + O_EUWT + (col << 2);
        qp[2 * h]     = eu;
        qp[2 * h + 1] = eu * muv;
    }
    if (l == 0 && ws >= 2) sred_h[8 + ws] = 0.0f;
    __syncthreads();                                        // P

    bool active0 = true, active1 = true;

    // ================= MAIN LOOP (v -> break -> u) =================
    for (int it = 0; it < MAX_ITER; ++it) {
        const float err0 = err_sum(sred0 + 8);
        const float err1 = err_sum(sred1 + 8);
        const bool last0 = active0 && (err0 < THRESH || it == MAX_ITER - 1);
        const bool last1 = active1 && (err1 < THRESH || it == MAX_ITER - 1);
        const bool anyLast = last0 || last1;
        const bool willEnd = (last0 || !active0) && (last1 || !active1);

        const __half2* cph = reinterpret_cast<const __half2*>(sE0h)
                           + (qr << 11) + cp;
        const float4* qw = reinterpret_cast<const float4*>(sm + O_EUWT) + (qr << 4);

        if (!anyLast) {
            // ===== LIGHT v-pass: av only =====
            float av0a = 0, av0b = 0, av1a = 0, av1b = 0;
            #pragma unroll
            for (int i = 0; i < 16; i++) {
                const float2 cf = __half22float2(cph[i << 7]);
                const float4 q  = qw[i];
                av0a = fmaf(cf.x, q.x, av0a); av0b = fmaf(cf.y, q.x, av0b);
                av1a = fmaf(cf.x, q.z, av1a); av1b = fmaf(cf.y, q.z, av1b);
            }
            if (qr) spartA[((qr - 1) << 7) + cp] = make_float4(av0a, av0b, av1a, av1b);
            __syncthreads();                                    // B4
            if (qr == 0) {
                #pragma unroll
                for (int t = 0; t < 3; t++) {
                    const float4 pa = spartA[(t << 7) + cp];
                    av0a += pa.x; av0b += pa.y; av1a += pa.z; av1b += pa.w;
                }
                const float2 kn0 = *reinterpret_cast<const float2*>(sm + O_SNU + 2 * cp);
                const float2 kn1 = *reinterpret_cast<const float2*>(sm + O_SNU + 256 + 2 * cp);
                if (active0)
                    *reinterpret_cast<float2*>(sm + O_SEV + 2 * cp)
                        = make_float2(__fdividef(kn0.x, av0a),
                                      __fdividef(kn0.y, av0b));
                if (active1)
                    *reinterpret_cast<float2*>(sm + O_SEV + 256 + 2 * cp)
                        = make_float2(__fdividef(kn1.x, av1a),
                                      __fdividef(kn1.y, av1b));
            }
            __syncthreads();                                    // B6
        } else {
            // ===== FULL v-pass: packed (av,ae) accumulators via f32x2 =====
            unsigned long long A0a = 0, A0b = 0, A1a = 0, A1b = 0;
            {
                const ulonglong2* qw2 = reinterpret_cast<const ulonglong2*>(qw);
                #pragma unroll
                for (int i = 0; i < 16; i++) {
                    const float2 cf = __half22float2(cph[i << 7]);
                    const ulonglong2 q2 = qw2[i];   // .x=(eu0,wt0) .y=(eu1,wt1)
                    unsigned long long cx, cy;
                    BCAST2(cx, cf.x);
                    BCAST2(cy, cf.y);
                    FFMA2(A0a, cx, q2.x);
                    FFMA2(A0b, cy, q2.x);
                    FFMA2(A1a, cx, q2.y);
                    FFMA2(A1b, cy, q2.y);
                }
            }
            if (qr) {
                // store packed pairs directly: (A0a, A1a) and (A0b, A1b)
                ulonglong2 sa; sa.x = A0a; sa.y = A1a;
                ulonglong2 sb; sb.x = A0b; sb.y = A1b;
                *reinterpret_cast<ulonglong2*>(&spartA[((qr - 1) << 7) + cp]) = sa;
                *reinterpret_cast<ulonglong2*>(&spartB[((qr - 1) << 7) + cp]) = sb;
            }
            __syncthreads();                                    // B4
            if (qr == 0) {
                #pragma unroll
                for (int t = 0; t < 3; t++) {
                    const ulonglong2 pa = *reinterpret_cast<const ulonglong2*>(
                        &spartA[(t << 7) + cp]);
                    const ulonglong2 pb = *reinterpret_cast<const ulonglong2*>(
                        &spartB[(t << 7) + cp]);
                    FADD2(A0a, pa.x); FADD2(A1a, pa.y);
                    FADD2(A0b, pb.x); FADD2(A1b, pb.y);
                }
                float av0a, ae0a, av0b, ae0b, av1a, ae1a, av1b, ae1b;
                UNPACK2(av0a, ae0a, A0a);
                UNPACK2(av0b, ae0b, A0b);
                UNPACK2(av1a, ae1a, A1a);
                UNPACK2(av1b, ae1b, A1b);
                const float2 kn0 = *reinterpret_cast<const float2*>(sm + O_SNU + 2 * cp);
                const float2 kn1 = *reinterpret_cast<const float2*>(sm + O_SNU + 256 + 2 * cp);
                if (active0) {
                    const float e0a = __fdividef(kn0.x, av0a);
                    const float e0b = __fdividef(kn0.y, av0b);
                    if (last0) {
                        *reinterpret_cast<float2*>(out + s0 * N_DIM + 2 * cp)
                            = make_float2(scale * e0a * ae0a, scale * e0b * ae0b);
                    } else {
                        *reinterpret_cast<float2*>(sm + O_SEV + 2 * cp)
                            = make_float2(e0a, e0b);
                    }
                }
                if (active1) {
                    const float e1a = __fdividef(kn1.x, av1a);
                    const float e1b = __fdividef(kn1.y, av1b);
                    if (last1) {
                        *reinterpret_cast<float2*>(out + s1 * N_DIM + 2 * cp)
                            = make_float2(scale * e1a * ae1a, scale * e1b * ae1b);
                    } else {
                        *reinterpret_cast<float2*>(sm + O_SEV + 256 + 2 * cp)
                            = make_float2(e1a, e1b);
                    }
                }
            }
            if (!willEnd) __syncthreads();                      // B6 (elided at end)
        }

        if (last0) active0 = false;
        if (last1) active1 = false;
        if (!active0 && !active1) break;

        // ---- u-pass for it+1: dot, multi-row butterfly, inline eu/wt ----
        const bool act_h = h ? active1 : active0;
        if (act_h) {
            const float4 evA = reinterpret_cast<const float4*>(sev_h)[2 * l];
            const float4 evB = reinterpret_cast<const float4*>(sev_h)[2 * l + 1];
            float p0, p1, p2, p3, p4, p5, p6, p7;
            float* pp[8] = {&p0, &p1, &p2, &p3, &p4, &p5, &p6, &p7};
            #pragma unroll
            for (int r = 0; r < 8; ++r) {
                const int row = (ws << 3) + r;
                const int4 hv = reinterpret_cast<const int4*>(sE0h + (row << 8))[l];
                const __half2* hp = reinterpret_cast<const __half2*>(&hv);
                const float2 f0 = __half22float2(hp[0]);
                const float2 f1 = __half22float2(hp[1]);
                const float2 f2 = __half22float2(hp[2]);
                const float2 f3 = __half22float2(hp[3]);
                *pp[r] = f0.x * evA.x + f0.y * evA.y + f1.x * evA.z + f1.y * evA.w
                       + f2.x * evB.x + f2.y * evB.y + f3.x * evB.z + f3.y * evB.w;
            }
            // multi-row butterfly: same pairwise tree as per-row xor16..1.
            const bool hi16 = (l & 16), hi8 = (l & 8), hi4 = (l & 4);
            float x0 = hi16 ? p0 : p4;
            float x1 = hi16 ? p1 : p5;
            float x2 = hi16 ? p2 : p6;
            float x3 = hi16 ? p3 : p7;
            x0 = __shfl_xor_sync(0xFFFFFFFFu, x0, 16);
            x1 = __shfl_xor_sync(0xFFFFFFFFu, x1, 16);
            x2 = __shfl_xor_sync(0xFFFFFFFFu, x2, 16);
            x3 = __shfl_xor_sync(0xFFFFFFFFu, x3, 16);
            const float q0 = (hi16 ? p4 : p0) + x0;
            const float q1 = (hi16 ? p5 : p1) + x1;
            const float q2 = (hi16 ? p6 : p2) + x2;
            const float q3 = (hi16 ? p7 : p3) + x3;
            float y0 = hi8 ? q0 : q2;
            float y1 = hi8 ? q1 : q3;
            y0 = __shfl_xor_sync(0xFFFFFFFFu, y0, 8);
            y1 = __shfl_xor_sync(0xFFFFFFFFu, y1, 8);
            const float t0 = (hi8 ? q2 : q0) + y0;
            const float t1 = (hi8 ? q3 : q1) + y1;
            float z = hi4 ? t0 : t1;
            z = __shfl_xor_sync(0xFFFFFFFFu, z, 4);
            float t = (hi4 ? t1 : t0) + z;
            t += __shfl_xor_sync(0xFFFFFFFFu, t, 2);
            t += __shfl_xor_sync(0xFFFFFFFFu, t, 1);
            // lane l holds rowsum of row ws*8 + ((l>>2)&7)
            float myDu = 0.0f;
            if ((l & 3) == 0) {
                const int row = (ws << 3) + ((l >> 2) & 7);
                const float unew = EPSV * (slm_h[row] - __logf(t));
                myDu = fabsf(unew - su_h[row]);
                su_h[row] = unew;
                const float eu = __fdividef(skmu_h[row], t);
                *reinterpret_cast<float2*>(sm + O_EUWT + (row << 2) + 2 * h)
                    = make_float2(eu, eu * smu_h[row]);
            }
            myDu += __shfl_xor_sync(0xFFFFFFFFu, myDu, 4);
            myDu += __shfl_xor_sync(0xFFFFFFFFu, myDu, 8);
            myDu += __shfl_xor_sync(0xFFFFFFFFu, myDu, 16);
            if (l == 0) sred_h[8 + ws] = myDu;
        }
        __syncthreads();                                        // B1
    }
}

// ---------------------------------------------------------------------------
// Launch: init normally; main with PDL.
// ---------------------------------------------------------------------------
extern "C" void kernel_launch(void* const* d_in, const int* in_sizes, int n_in,
                              void* d_out, int out_size) {
    const float* mu = nullptr;
    const float* nu = nullptr;
    const float* C  = nullptr;
    for (int i = 0; i < n_in; ++i) {
        if (in_sizes[i] == S_TOT * B_DIM)      mu = (const float*)d_in[i];
        else if (in_sizes[i] == S_TOT * N_DIM) nu = (const float*)d_in[i];
        else if (in_sizes[i] == B_DIM * N_DIM) C  = (const float*)d_in[i];
    }
    float* out = (float*)d_out;

    const int smem_bytes = SMEM_FLOATS * sizeof(float);   // ~51.1 KB -> 4 blk/SM
    cudaFuncSetAttribute(ot_main_kernel,
                         cudaFuncAttributeMaxDynamicSharedMemorySize, smem_bytes);

    ot_init_kernel<<<16, 256>>>(C);

    cudaLaunchConfig_t cfg = {};
    cfg.gridDim  = dim3(S_TOT / 2, 1, 1);
    cfg.blockDim = dim3(THREADS, 1, 1);
    cfg.dynamicSmemBytes = smem_bytes;
    cfg.stream = 0;
    cudaLaunchAttribute attr[1];
    attr[0].id = cudaLaunchAttributeProgrammaticStreamSerialization;
    attr[0].val.programmaticStreamSerializationAllowed = 1;
    cfg.attrs = attr;
    cfg.numAttrs = 1;
    cudaLaunchKernelEx(&cfg, ot_main_kernel, mu, nu, out);
}